// round 11
// baseline (speedup 1.0000x reference)
#include <cuda_runtime.h>
#include <cuda_pipeline.h>

#define S  512
#define S2 (S*S)
#define NBATCH 32
#define NBLK_TOTAL 4096u
#define TROWS 67            // halo rows: 64 + 3
#define TCW   40            // smem row width (floats), 16B-aligned window

// Global accumulators (zero at load; finalize resets them each run)
__device__ double g_acc[2] = {0.0, 0.0};         // [0]=sum|cont|, [1]=sum|pois|
__device__ double g_bc4[NBATCH * 4] = {0.0};     // per-batch per-edge signed sums
__device__ unsigned int g_count = 0u;

// Per-thread 8-row strip. Fields: 0=u, 1=v, 2=p, 3=q. smem col c <-> gx = bx*32-4+c.
template<bool INT>
__device__ __forceinline__ void tile_compute(
    const float (*__restrict__ sf)[TROWS][TCW],
    int tx, int ty, int i0, int j0, float& accC, float& accP)
{
    const int lc  = tx + 5;          // smem col of global column j
    const int lr0 = ty * 8 + 2;
    const int ir0 = i0 + ty * 8;
    const int j   = j0 + tx;

    // ---- rolled state at row lr0 ----
    float u_m2 = sf[0][lr0][lc-2], u_m1 = sf[0][lr0][lc-1], u_0 = sf[0][lr0][lc], u_p1 = sf[0][lr0][lc+1];
    float v_m1 = sf[1][lr0][lc-1], v_0 = sf[1][lr0][lc], v_p1 = sf[1][lr0][lc+1];
    float p_m1 = sf[2][lr0][lc-1], p_0 = sf[2][lr0][lc], p_p1 = sf[2][lr0][lc+1];
    float q_m1 = sf[3][lr0][lc-1], q_0 = sf[3][lr0][lc], q_p1 = sf[3][lr0][lc+1];

    float uN_0 = sf[0][lr0-1][lc], uN_m1 = sf[0][lr0-1][lc-1];
    float vN_m1 = sf[1][lr0-1][lc-1], vN_0 = sf[1][lr0-1][lc], vN_p1 = sf[1][lr0-1][lc+1];
    float p_N = sf[2][lr0-1][lc];
    float q_N = sf[3][lr0-1][lc];
    float vNN_0 = sf[1][lr0-2][lc];

    // ---- flux init between rows ir0-1 and ir0 ----
    float prodN  = (0.5f*(vN_0 + vN_p1)) * (0.5f*(uN_0 + u_0));
    float prodNm = (0.5f*(vN_m1 + vN_0)) * (0.5f*(uN_m1 + u_m1));
    float fn_prev   = prodN  - (u_0  - uN_0);
    float fn_prev_m = prodNm - (u_m1 - uN_m1);
    float ga = 0.5f*(vNN_0 + vN_0);
    float gn_prev = ga*ga - (vN_0 - vNN_0);
    float geN1 = prodN  - (vN_p1 - vN_0);
    float geN0 = prodNm - (vN_0  - vN_m1);
    float gaa  = 0.5f*(vN_0 + v_0);
    float gnN1 = gaa*gaa - (v_0 - vN_0);
    float dvdtN = (-(geN1 - geN0) - (gnN1 - gn_prev) - (p_0 - p_N)) * 100.0f;
    float vn_prev = vN_0 + dvdtN * 0.001f;
    if (!INT) { if (ir0 - 1 < 1) vn_prev = vN_0; }
    gn_prev = gnN1;
    float vN_roll = vN_0;

    #pragma unroll
    for (int k = 0; k < 8; k++) {
        const int lr = lr0 + k;
        const int i  = ir0 + k;
        // next-row loads (16 LDS.32)
        float uS_m2 = sf[0][lr+1][lc-2], uS_m1 = sf[0][lr+1][lc-1], uS_0 = sf[0][lr+1][lc], uS_p1 = sf[0][lr+1][lc+1];
        float vS_m1 = sf[1][lr+1][lc-1], vS_0 = sf[1][lr+1][lc], vS_p1 = sf[1][lr+1][lc+1];
        float pS_m1 = sf[2][lr+1][lc-1], pS_0 = sf[2][lr+1][lc], pS_p1 = sf[2][lr+1][lc+1];
        float qS_m1 = sf[3][lr+1][lc-1], qS_0 = sf[3][lr+1][lc], qS_p1 = sf[3][lr+1][lc+1];

        // horizontal u fluxes (row lr)
        float ea = 0.5f*(u_m2 + u_m1); float fe0m = ea*ea - (u_m1 - u_m2);
        float eb = 0.5f*(u_m1 + u_0);  float fe0  = eb*eb - (u_0  - u_m1);
        float ec = 0.5f*(u_0  + u_p1); float fe1  = ec*ec - (u_p1 - u_0);
        // shared cross products
        float prod  = (0.5f*(v_0  + v_p1)) * (0.5f*(u_0  + uS_0));
        float prodm = (0.5f*(v_m1 + v_0))  * (0.5f*(u_m1 + uS_m1));
        float fn1  = prod  - (uS_0  - u_0);
        float fn1m = prodm - (uS_m1 - u_m1);
        float ge1  = prod  - (v_p1 - v_0);
        float ge0  = prodm - (v_0  - v_m1);
        float gna = 0.5f*(v_0 + vS_0); float gn1 = gna*gna - (vS_0 - v_0);

        float dudt  = (-(fe1 - fe0)  - (fn1  - fn_prev)   - (p_p1 - p_0)) * 100.0f;
        float dudtm = (-(fe0 - fe0m) - (fn1m - fn_prev_m) - (p_0 - p_m1)) * 100.0f;
        float dvdt  = (-(ge1 - ge0)  - (gn1  - gn_prev)   - (pS_0 - p_0)) * 100.0f;

        float un  = u_0  + dudt  * 0.001f;
        float unm = u_m1 + dudtm * 0.001f;
        float vn  = v_0  + dvdt  * 0.001f;
        if (!INT) {
            if (j > 509 || i > 510)     un  = u_0;
            if (j - 1 < 1 || i > 510)   unm = u_m1;
            if (i > 509)                vn  = v_0;
        }

        float cont  = (u_0 - u_m1 + v_0 - vN_roll) * 100.0f;
        float bconv = ((un - unm) + (vn - vn_prev)) * 100000.0f;
        float lap   = 4.0f*(q_0 - p_0) - (q_p1 - p_p1) - (q_m1 - p_m1)
                    - (qS_0 - pS_0) - (q_N - p_N);
        float pois  = fmaf(lap, 10000.0f, bconv);
        if (INT || (i <= 510 && j <= 510)) {
            accC += fabsf(cont);
            accP += fabsf(pois);
        }

        // roll (center -> north BEFORE overwriting center)
        fn_prev = fn1; fn_prev_m = fn1m; gn_prev = gn1; vn_prev = vn;
        q_N = q_0; p_N = p_0; vN_roll = v_0;
        u_m2 = uS_m2; u_m1 = uS_m1; u_0 = uS_0; u_p1 = uS_p1;
        v_m1 = vS_m1; v_0 = vS_0; v_p1 = vS_p1;
        p_m1 = pS_m1; p_0 = pS_0;   p_p1 = pS_p1;
        q_m1 = qS_m1; q_0 = qS_0;   q_p1 = qS_p1;
    }
}

__global__ __launch_bounds__(256, 4) void pil_kernel(const float* __restrict__ gen,
                                                     const float* __restrict__ pn,
                                                     float* __restrict__ out) {
    // planar halo tiles: sf[field][row][col], col window gx = bx*32-4 .. bx*32+35
    __shared__ __align__(16) float sf[4][TROWS][TCW];
    __shared__ float redC[8], redP[8];
    __shared__ double dred[8];
    __shared__ unsigned int s_ticket;

    const int bx = blockIdx.x, by = blockIdx.y, b = blockIdx.z;
    const int i0 = 1 + by * 64;
    const int j0 = 1 + bx * 32;
    const int tid = threadIdx.x;
    const int tx = tid & 31, ty = tid >> 5;   // ty = warp id, 0..7

    const float* u = gen + (size_t)b * 3 * S2;
    const float* q = pn + (size_t)b * S2;
    const int colbase = j0 - 5;               // = bx*32 - 4, 16B aligned

    const bool colInt = (bx >= 1) && (bx <= 14);
    const bool rowInt = (by >= 1) && (by <= 6);

    // ---- load: each warp fills its OWN 11 rows (strip + halo) of all 4 fields.
    if (colInt) {
        // cp.async 16B segments. Lane f = tx>>3 covers field f, segment s = tx&7;
        // lanes 0..7 additionally cover segments 8..9 (f2 = tx>>1, s2 = 8+(tx&1)).
        const int f1 = tx >> 3, s1 = tx & 7;
        const float* fp1 = (f1 < 3) ? (u + (size_t)f1 * S2) : q;
        const int f2 = tx >> 1, s2 = 8 + (tx & 1);
        const float* fp2 = (f2 < 3) ? (u + (size_t)f2 * S2) : q;
        const bool lo8 = (tx < 8);
        if (rowInt) {
            // gy in [63,449]: no clamps; constant-stride addressing
            const int off0 = (i0 - 2 + ty * 8) * S + colbase;
            #pragma unroll
            for (int rl = 0; rl < 11; rl++) {
                int R = ty * 8 + rl;
                const int off = off0 + rl * S;
                __pipeline_memcpy_async(&sf[f1][R][s1 * 4], fp1 + off + s1 * 4, 16);
                if (lo8)
                    __pipeline_memcpy_async(&sf[f2][R][s2 * 4], fp2 + off + s2 * 4, 16);
            }
        } else {
            #pragma unroll
            for (int rl = 0; rl < 11; rl++) {
                int R = ty * 8 + rl;
                int gy = i0 - 2 + R; gy = max(0, min(S - 1, gy));
                const int off = gy * S + colbase;
                __pipeline_memcpy_async(&sf[f1][R][s1 * 4], fp1 + off + s1 * 4, 16);
                if (lo8)
                    __pipeline_memcpy_async(&sf[f2][R][s2 * 4], fp2 + off + s2 * 4, 16);
            }
        }
        __pipeline_commit();
        __pipeline_wait_prior(0);
        __syncwarp();
    } else {
        // scalar clamped path (bx = 0 or 15)
        const float* v = u + S2;
        const float* p = v + S2;
        int c1 = tx, c2 = 32 + tx;                       // cols; c2 valid for tx<8
        int gx1 = colbase + c1; gx1 = max(0, min(S - 1, gx1));
        int gx2 = colbase + c2; gx2 = max(0, min(S - 1, gx2));
        for (int rl = 0; rl < 11; rl++) {
            int R = ty * 8 + rl;
            int gy = i0 - 2 + R; gy = max(0, min(S - 1, gy));
            const int ro = gy * S;
            sf[0][R][c1] = u[ro + gx1];
            sf[1][R][c1] = v[ro + gx1];
            sf[2][R][c1] = p[ro + gx1];
            sf[3][R][c1] = q[ro + gx1];
            if (tx < 8) {
                sf[0][R][c2] = u[ro + gx2];
                sf[1][R][c2] = v[ro + gx2];
                sf[2][R][c2] = p[ro + gx2];
                sf[3][R][c2] = q[ro + gx2];
            }
        }
        __syncwarp();
    }

    float accC = 0.0f, accP = 0.0f;
    const bool interior = colInt && rowInt;
    if (interior) {
        tile_compute<true >(sf, tx, ty, i0, j0, accC, accP);
    } else {
        tile_compute<false>(sf, tx, ty, i0, j0, accC, accP);

        // BC sums read rows owned by other warps -> block-uniform barrier here.
        __syncthreads();

        // ---- boundary-condition edge sums (edge blocks, from smem) ----
        float es = 0.0f; int eidx = -1;
        if (tid < 32) {                       // top/bottom: 32 cols
            int jj = j0 + tid, cc = tid + 5;
            if (by == 0) {
                eidx = 0;
                if (jj <= 509) es += sf[0][1][cc] + sf[0][2][cc];   // u rows 0,1
                if (jj <= 510) es += sf[1][1][cc] + sf[2][1][cc];   // v,p row 0
            } else if (by == 7) {
                eidx = 1;
                if (jj <= 509) es += 2.0f - (sf[0][63][cc] + sf[0][64][cc]); // u rows 510,511
                if (jj <= 510) es += sf[1][64][cc] + sf[2][64][cc];          // v,p row 511
            }
        } else if (tid < 96) {                // left/right: 64 rows (2 warps)
            int lane = tid - 32;              // 0..63
            int ii = i0 + lane, lrr = lane + 2;
            if (bx == 0) {                    // gx=0 -> c=4, gx=1 -> c=5
                eidx = 2;
                if (ii <= 509) es += sf[1][lrr][4] + sf[1][lrr][5];
                if (ii <= 510) es += sf[0][lrr][4] + sf[2][lrr][4];
            } else if (bx == 15) {            // gx=510 -> c=34, gx=511 -> c=35
                eidx = 3;
                if (ii <= 509) es += sf[1][lrr][35] + sf[1][lrr][34];
                if (ii <= 510) es += sf[0][lrr][35] + sf[2][lrr][35];
            }
        }
        if (eidx >= 0) {                      // warp-uniform per warp
            #pragma unroll
            for (int off = 16; off > 0; off >>= 1)
                es += __shfl_down_sync(0xFFFFFFFFu, es, off);
            if ((tid & 31) == 0)
                atomicAdd(&g_bc4[b * 4 + eidx], (double)es);
        }
    }

    // ---- block reduction of residual sums ----
    #pragma unroll
    for (int off = 16; off > 0; off >>= 1) {
        accC += __shfl_down_sync(0xFFFFFFFFu, accC, off);
        accP += __shfl_down_sync(0xFFFFFFFFu, accP, off);
    }
    if (tx == 0) { redC[ty] = accC; redP[ty] = accP; }
    __syncthreads();
    if (ty == 0) {
        float rc = (tx < 8) ? redC[tx] : 0.0f;
        float rp = (tx < 8) ? redP[tx] : 0.0f;
        #pragma unroll
        for (int off = 4; off > 0; off >>= 1) {
            rc += __shfl_down_sync(0xFFFFFFFFu, rc, off);
            rp += __shfl_down_sync(0xFFFFFFFFu, rp, off);
        }
        if (tx == 0) {
            atomicAdd(&g_acc[0], (double)rc);
            atomicAdd(&g_acc[1], (double)rp);
        }
    }

    // ---- last-block finalize ----
    __threadfence();
    if (tid == 0) s_ticket = atomicAdd(&g_count, 1u);
    __syncthreads();
    if (s_ticket == NBLK_TOTAL - 1u) {
        double mybc = 0.0;
        if (tid < NBATCH * 4)
            mybc = fabs(atomicAdd(&g_bc4[tid], 0.0));
        #pragma unroll
        for (int off = 16; off > 0; off >>= 1)
            mybc += __shfl_down_sync(0xFFFFFFFFu, mybc, off);
        if (tx == 0) dred[ty] = mybc;
        __syncthreads();
        if (tid == 0) {
            double bc = 0.0;
            #pragma unroll
            for (int kk = 0; kk < 8; kk++) bc += dred[kk];
            double C = atomicAdd(&g_acc[0], 0.0);
            double P = atomicAdd(&g_acc[1], 0.0);
            double denom = 32.0 * 510.0 * 510.0;
            out[0] = (float)(0.4 * (C / denom) + 0.2 * bc + (1.0 - 0.4 - 0.2) * (P / denom));
            g_acc[0] = 0.0; g_acc[1] = 0.0;
        }
        if (tid < NBATCH * 4) g_bc4[tid] = 0.0;
        __threadfence();
        __syncthreads();
        if (tid == 0) g_count = 0u;
    }
}

extern "C" void kernel_launch(void* const* d_in, const int* in_sizes, int n_in,
                              void* d_out, int out_size) {
    const float* gen = (const float*)d_in[0];
    const float* pn  = (const float*)d_in[1];
    float* out = (float*)d_out;
    dim3 grid(16, 8, NBATCH);   // 16 x 8 x 32 = 4096 blocks
    pil_kernel<<<grid, 256>>>(gen, pn, out);
}

// round 12
// speedup vs baseline: 1.1084x; 1.1084x over previous
#include <cuda_runtime.h>
#include <cuda_pipeline.h>

#define S  512
#define S2 (S*S)
#define NBATCH 32
#define NBLK_TOTAL 4096u
#define TROWS 67            // halo rows: 64 + 3
#define TCW   40            // smem row width (floats), 16B-aligned window

// Global accumulators (zero at load; finalize resets them each run)
__device__ double g_acc[2] = {0.0, 0.0};         // [0]=sum|cont|, [1]=sum|pois|
__device__ double g_bc4[NBATCH * 4] = {0.0};     // per-batch per-edge signed sums
__device__ unsigned int g_count = 0u;

// Per-thread 8-row strip. Fields: 0=u, 1=v, 2=p, 3=q. smem col c <-> gx = bx*32-4+c.
template<bool INT>
__device__ __forceinline__ void tile_compute(
    const float (*__restrict__ sf)[TROWS][TCW],
    int tx, int ty, int i0, int j0, float& accC, float& accP)
{
    const int lc  = tx + 5;          // smem col of global column j
    const int lr0 = ty * 8 + 2;
    const int ir0 = i0 + ty * 8;
    const int j   = j0 + tx;

    // ---- rolled state at row lr0 ----
    float u_m2 = sf[0][lr0][lc-2], u_m1 = sf[0][lr0][lc-1], u_0 = sf[0][lr0][lc], u_p1 = sf[0][lr0][lc+1];
    float v_m1 = sf[1][lr0][lc-1], v_0 = sf[1][lr0][lc], v_p1 = sf[1][lr0][lc+1];
    float p_m1 = sf[2][lr0][lc-1], p_0 = sf[2][lr0][lc], p_p1 = sf[2][lr0][lc+1];
    float q_m1 = sf[3][lr0][lc-1], q_0 = sf[3][lr0][lc], q_p1 = sf[3][lr0][lc+1];

    float uN_0 = sf[0][lr0-1][lc], uN_m1 = sf[0][lr0-1][lc-1];
    float vN_m1 = sf[1][lr0-1][lc-1], vN_0 = sf[1][lr0-1][lc], vN_p1 = sf[1][lr0-1][lc+1];
    float p_N = sf[2][lr0-1][lc];
    float q_N = sf[3][lr0-1][lc];
    float vNN_0 = sf[1][lr0-2][lc];

    // ---- flux init between rows ir0-1 and ir0 ----
    float prodN  = (0.5f*(vN_0 + vN_p1)) * (0.5f*(uN_0 + u_0));
    float prodNm = (0.5f*(vN_m1 + vN_0)) * (0.5f*(uN_m1 + u_m1));
    float fn_prev   = prodN  - (u_0  - uN_0);
    float fn_prev_m = prodNm - (u_m1 - uN_m1);
    float ga = 0.5f*(vNN_0 + vN_0);
    float gn_prev = ga*ga - (vN_0 - vNN_0);
    float geN1 = prodN  - (vN_p1 - vN_0);
    float geN0 = prodNm - (vN_0  - vN_m1);
    float gaa  = 0.5f*(vN_0 + v_0);
    float gnN1 = gaa*gaa - (v_0 - vN_0);
    float dvdtN = (-(geN1 - geN0) - (gnN1 - gn_prev) - (p_0 - p_N)) * 100.0f;
    float vn_prev = vN_0 + dvdtN * 0.001f;
    if (!INT) { if (ir0 - 1 < 1) vn_prev = vN_0; }
    gn_prev = gnN1;
    float vN_roll = vN_0;

    #pragma unroll
    for (int k = 0; k < 8; k++) {
        const int lr = lr0 + k;
        const int i  = ir0 + k;
        // next-row loads (16 LDS.32)
        float uS_m2 = sf[0][lr+1][lc-2], uS_m1 = sf[0][lr+1][lc-1], uS_0 = sf[0][lr+1][lc], uS_p1 = sf[0][lr+1][lc+1];
        float vS_m1 = sf[1][lr+1][lc-1], vS_0 = sf[1][lr+1][lc], vS_p1 = sf[1][lr+1][lc+1];
        float pS_m1 = sf[2][lr+1][lc-1], pS_0 = sf[2][lr+1][lc], pS_p1 = sf[2][lr+1][lc+1];
        float qS_m1 = sf[3][lr+1][lc-1], qS_0 = sf[3][lr+1][lc], qS_p1 = sf[3][lr+1][lc+1];

        // horizontal u fluxes (row lr)
        float ea = 0.5f*(u_m2 + u_m1); float fe0m = ea*ea - (u_m1 - u_m2);
        float eb = 0.5f*(u_m1 + u_0);  float fe0  = eb*eb - (u_0  - u_m1);
        float ec = 0.5f*(u_0  + u_p1); float fe1  = ec*ec - (u_p1 - u_0);
        // shared cross products
        float prod  = (0.5f*(v_0  + v_p1)) * (0.5f*(u_0  + uS_0));
        float prodm = (0.5f*(v_m1 + v_0))  * (0.5f*(u_m1 + uS_m1));
        float fn1  = prod  - (uS_0  - u_0);
        float fn1m = prodm - (uS_m1 - u_m1);
        float ge1  = prod  - (v_p1 - v_0);
        float ge0  = prodm - (v_0  - v_m1);
        float gna = 0.5f*(v_0 + vS_0); float gn1 = gna*gna - (vS_0 - v_0);

        float dudt  = (-(fe1 - fe0)  - (fn1  - fn_prev)   - (p_p1 - p_0)) * 100.0f;
        float dudtm = (-(fe0 - fe0m) - (fn1m - fn_prev_m) - (p_0 - p_m1)) * 100.0f;
        float dvdt  = (-(ge1 - ge0)  - (gn1  - gn_prev)   - (pS_0 - p_0)) * 100.0f;

        float un  = u_0  + dudt  * 0.001f;
        float unm = u_m1 + dudtm * 0.001f;
        float vn  = v_0  + dvdt  * 0.001f;
        if (!INT) {
            if (j > 509 || i > 510)     un  = u_0;
            if (j - 1 < 1 || i > 510)   unm = u_m1;
            if (i > 509)                vn  = v_0;
        }

        float cont  = (u_0 - u_m1 + v_0 - vN_roll) * 100.0f;
        float bconv = ((un - unm) + (vn - vn_prev)) * 100000.0f;
        float lap   = 4.0f*(q_0 - p_0) - (q_p1 - p_p1) - (q_m1 - p_m1)
                    - (qS_0 - pS_0) - (q_N - p_N);
        float pois  = fmaf(lap, 10000.0f, bconv);
        if (INT || (i <= 510 && j <= 510)) {
            accC += fabsf(cont);
            accP += fabsf(pois);
        }

        // roll (center -> north BEFORE overwriting center)
        fn_prev = fn1; fn_prev_m = fn1m; gn_prev = gn1; vn_prev = vn;
        q_N = q_0; p_N = p_0; vN_roll = v_0;
        u_m2 = uS_m2; u_m1 = uS_m1; u_0 = uS_0; u_p1 = uS_p1;
        v_m1 = vS_m1; v_0 = vS_0; v_p1 = vS_p1;
        p_m1 = pS_m1; p_0 = pS_0;   p_p1 = pS_p1;
        q_m1 = qS_m1; q_0 = qS_0;   q_p1 = qS_p1;
    }
}

__global__ __launch_bounds__(256, 5) void pil_kernel(const float* __restrict__ gen,
                                                     const float* __restrict__ pn,
                                                     float* __restrict__ out) {
    // planar halo tiles: sf[field][row][col], col window gx = bx*32-4 .. bx*32+35
    __shared__ __align__(16) float sf[4][TROWS][TCW];
    __shared__ float redC[8], redP[8];
    __shared__ double dred[8];
    __shared__ unsigned int s_ticket;

    const int bx = blockIdx.x, by = blockIdx.y, b = blockIdx.z;
    const int i0 = 1 + by * 64;
    const int j0 = 1 + bx * 32;
    const int tid = threadIdx.x;
    const int tx = tid & 31, ty = tid >> 5;   // ty = warp id, 0..7

    const float* u = gen + (size_t)b * 3 * S2;
    const float* q = pn + (size_t)b * S2;
    const int colbase = j0 - 5;               // = bx*32 - 4, 16B aligned

    const bool colInt = (bx >= 1) && (bx <= 14);
    const bool rowInt = (by >= 1) && (by <= 6);

    // ---- load: deduplicated — warp ty loads rows ty*8..ty*8+7; warps 0..2 take
    //      tail rows 64..66. One wait + one barrier; no duplicated L2 traffic.
    if (colInt) {
        // cp.async 16B segments. Lane f = tx>>3 covers field f, segment s = tx&7;
        // lanes 0..7 additionally cover segments 8..9 (f2 = tx>>1, s2 = 8+(tx&1)).
        const int f1 = tx >> 3, s1 = tx & 7;
        const float* fp1 = (f1 < 3) ? (u + (size_t)f1 * S2) : q;
        const int f2 = tx >> 1, s2 = 8 + (tx & 1);
        const float* fp2 = (f2 < 3) ? (u + (size_t)f2 * S2) : q;
        const bool lo8 = (tx < 8);
        if (rowInt) {
            // gy in [63,449]: no clamps; constant-stride addressing
            const int off0 = (i0 - 2 + ty * 8) * S + colbase;
            #pragma unroll
            for (int rl = 0; rl < 8; rl++) {
                int R = ty * 8 + rl;
                const int off = off0 + rl * S;
                __pipeline_memcpy_async(&sf[f1][R][s1 * 4], fp1 + off + s1 * 4, 16);
                if (lo8)
                    __pipeline_memcpy_async(&sf[f2][R][s2 * 4], fp2 + off + s2 * 4, 16);
            }
            if (ty < 3) {
                int R = 64 + ty;
                const int off = (i0 - 2 + R) * S + colbase;
                __pipeline_memcpy_async(&sf[f1][R][s1 * 4], fp1 + off + s1 * 4, 16);
                if (lo8)
                    __pipeline_memcpy_async(&sf[f2][R][s2 * 4], fp2 + off + s2 * 4, 16);
            }
        } else {
            #pragma unroll
            for (int rl = 0; rl < 8; rl++) {
                int R = ty * 8 + rl;
                int gy = i0 - 2 + R; gy = max(0, min(S - 1, gy));
                const int off = gy * S + colbase;
                __pipeline_memcpy_async(&sf[f1][R][s1 * 4], fp1 + off + s1 * 4, 16);
                if (lo8)
                    __pipeline_memcpy_async(&sf[f2][R][s2 * 4], fp2 + off + s2 * 4, 16);
            }
            if (ty < 3) {
                int R = 64 + ty;
                int gy = i0 - 2 + R; gy = max(0, min(S - 1, gy));
                const int off = gy * S + colbase;
                __pipeline_memcpy_async(&sf[f1][R][s1 * 4], fp1 + off + s1 * 4, 16);
                if (lo8)
                    __pipeline_memcpy_async(&sf[f2][R][s2 * 4], fp2 + off + s2 * 4, 16);
            }
        }
        __pipeline_commit();
        __pipeline_wait_prior(0);
    } else {
        // scalar clamped path (bx = 0 or 15)
        const float* v = u + S2;
        const float* p = v + S2;
        int c1 = tx, c2 = 32 + tx;                       // cols; c2 valid for tx<8
        int gx1 = colbase + c1; gx1 = max(0, min(S - 1, gx1));
        int gx2 = colbase + c2; gx2 = max(0, min(S - 1, gx2));
        int nrows = (ty < 3) ? 9 : 8;
        for (int rl = 0; rl < nrows; rl++) {
            int R = (rl < 8) ? (ty * 8 + rl) : (64 + ty);
            int gy = i0 - 2 + R; gy = max(0, min(S - 1, gy));
            const int ro = gy * S;
            sf[0][R][c1] = u[ro + gx1];
            sf[1][R][c1] = v[ro + gx1];
            sf[2][R][c1] = p[ro + gx1];
            sf[3][R][c1] = q[ro + gx1];
            if (tx < 8) {
                sf[0][R][c2] = u[ro + gx2];
                sf[1][R][c2] = v[ro + gx2];
                sf[2][R][c2] = p[ro + gx2];
                sf[3][R][c2] = q[ro + gx2];
            }
        }
    }
    __syncthreads();          // all rows visible block-wide

    float accC = 0.0f, accP = 0.0f;
    const bool interior = colInt && rowInt;
    if (interior) {
        tile_compute<true >(sf, tx, ty, i0, j0, accC, accP);
    } else {
        tile_compute<false>(sf, tx, ty, i0, j0, accC, accP);

        // ---- boundary-condition edge sums (edge blocks, from smem) ----
        float es = 0.0f; int eidx = -1;
        if (tid < 32) {                       // top/bottom: 32 cols
            int jj = j0 + tid, cc = tid + 5;
            if (by == 0) {
                eidx = 0;
                if (jj <= 509) es += sf[0][1][cc] + sf[0][2][cc];   // u rows 0,1
                if (jj <= 510) es += sf[1][1][cc] + sf[2][1][cc];   // v,p row 0
            } else if (by == 7) {
                eidx = 1;
                if (jj <= 509) es += 2.0f - (sf[0][63][cc] + sf[0][64][cc]); // u rows 510,511
                if (jj <= 510) es += sf[1][64][cc] + sf[2][64][cc];          // v,p row 511
            }
        } else if (tid < 96) {                // left/right: 64 rows (2 warps)
            int lane = tid - 32;              // 0..63
            int ii = i0 + lane, lrr = lane + 2;
            if (bx == 0) {                    // gx=0 -> c=4, gx=1 -> c=5
                eidx = 2;
                if (ii <= 509) es += sf[1][lrr][4] + sf[1][lrr][5];
                if (ii <= 510) es += sf[0][lrr][4] + sf[2][lrr][4];
            } else if (bx == 15) {            // gx=510 -> c=34, gx=511 -> c=35
                eidx = 3;
                if (ii <= 509) es += sf[1][lrr][35] + sf[1][lrr][34];
                if (ii <= 510) es += sf[0][lrr][35] + sf[2][lrr][35];
            }
        }
        if (eidx >= 0) {                      // warp-uniform per warp
            #pragma unroll
            for (int off = 16; off > 0; off >>= 1)
                es += __shfl_down_sync(0xFFFFFFFFu, es, off);
            if ((tid & 31) == 0)
                atomicAdd(&g_bc4[b * 4 + eidx], (double)es);
        }
    }

    // ---- block reduction of residual sums ----
    #pragma unroll
    for (int off = 16; off > 0; off >>= 1) {
        accC += __shfl_down_sync(0xFFFFFFFFu, accC, off);
        accP += __shfl_down_sync(0xFFFFFFFFu, accP, off);
    }
    if (tx == 0) { redC[ty] = accC; redP[ty] = accP; }
    __syncthreads();
    if (ty == 0) {
        float rc = (tx < 8) ? redC[tx] : 0.0f;
        float rp = (tx < 8) ? redP[tx] : 0.0f;
        #pragma unroll
        for (int off = 4; off > 0; off >>= 1) {
            rc += __shfl_down_sync(0xFFFFFFFFu, rc, off);
            rp += __shfl_down_sync(0xFFFFFFFFu, rp, off);
        }
        if (tx == 0) {
            atomicAdd(&g_acc[0], (double)rc);
            atomicAdd(&g_acc[1], (double)rp);
        }
    }

    // ---- last-block finalize ----
    __threadfence();
    if (tid == 0) s_ticket = atomicAdd(&g_count, 1u);
    __syncthreads();
    if (s_ticket == NBLK_TOTAL - 1u) {
        double mybc = 0.0;
        if (tid < NBATCH * 4)
            mybc = fabs(atomicAdd(&g_bc4[tid], 0.0));
        #pragma unroll
        for (int off = 16; off > 0; off >>= 1)
            mybc += __shfl_down_sync(0xFFFFFFFFu, mybc, off);
        if (tx == 0) dred[ty] = mybc;
        __syncthreads();
        if (tid == 0) {
            double bc = 0.0;
            #pragma unroll
            for (int kk = 0; kk < 8; kk++) bc += dred[kk];
            double C = atomicAdd(&g_acc[0], 0.0);
            double P = atomicAdd(&g_acc[1], 0.0);
            double denom = 32.0 * 510.0 * 510.0;
            out[0] = (float)(0.4 * (C / denom) + 0.2 * bc + (1.0 - 0.4 - 0.2) * (P / denom));
            g_acc[0] = 0.0; g_acc[1] = 0.0;
        }
        if (tid < NBATCH * 4) g_bc4[tid] = 0.0;
        __threadfence();
        __syncthreads();
        if (tid == 0) g_count = 0u;
    }
}

extern "C" void kernel_launch(void* const* d_in, const int* in_sizes, int n_in,
                              void* d_out, int out_size) {
    const float* gen = (const float*)d_in[0];
    const float* pn  = (const float*)d_in[1];
    float* out = (float*)d_out;
    dim3 grid(16, 8, NBATCH);   // 16 x 8 x 32 = 4096 blocks
    pil_kernel<<<grid, 256>>>(gen, pn, out);
}

// round 13
// speedup vs baseline: 1.1431x; 1.0313x over previous
#include <cuda_runtime.h>
#include <cuda_pipeline.h>

#define S  512
#define S2 (S*S)
#define NBATCH 32
#define NBLK_TOTAL 4096u
#define TROWS 35            // halo rows: 32 + 3
#define TCW   72            // smem row width (floats): 64 + halo, 16B-aligned

// Global accumulators (zero at load; finalize resets them each run)
__device__ double g_acc[2] = {0.0, 0.0};         // [0]=sum|cont|, [1]=sum|pois|
__device__ double g_bc4[NBATCH * 4] = {0.0};     // per-batch per-edge signed sums
__device__ unsigned int g_count = 0u;

// Per-thread strip: 2 columns (jA, jB) x 4 rows. Fields: 0=u,1=v,2=p,3=q.
// smem col c <-> gx = bx*64 - 4 + c ; col jA = j0+2*tx sits at c = 5+2*tx (odd),
// so all stencil windows tile into even-aligned float2 (LDS.64) pairs.
template<bool INT>
__device__ __forceinline__ void tile_compute(
    const float (*__restrict__ sf)[TROWS][TCW],
    int tx, int ty, int i0, int j0, float& accC, float& accP)
{
    const int e   = 2 + 2 * tx;      // even base col: pairs at e, e+2, e+4
    const int lr0 = ty * 4 + 2;
    const int ir0 = i0 + ty * 4;
    const int jA  = j0 + 2 * tx;
    const int jB  = jA + 1;

#define LD2(F,R,C) (*(const float2*)(&sf[F][R][C]))

    float2 t;
    // ---- current row lr0: u(jA-2..jA+2), v/p/d(jA-1..jB+1) ----
    t = LD2(0,lr0,e);    float u0 = t.y;
    t = LD2(0,lr0,e+2);  float u1 = t.x, u2 = t.y;
    t = LD2(0,lr0,e+4);  float u3 = t.x, u4 = t.y;
    t = LD2(1,lr0,e+2);  float v0 = t.x, v1 = t.y;
    t = LD2(1,lr0,e+4);  float v2 = t.x, v3 = t.y;
    t = LD2(2,lr0,e+2);  float p0 = t.x, p1 = t.y;
    t = LD2(2,lr0,e+4);  float p2 = t.x, p3 = t.y;
    t = LD2(3,lr0,e+2);  float d0 = t.x - p0, d1 = t.y - p1;
    t = LD2(3,lr0,e+4);  float d2 = t.x - p2, d3 = t.y - p3;
    // ---- row lr0-1 (north) ----
    t = LD2(0,lr0-1,e+2); float uN1 = t.x, uN2 = t.y;      // uN(jA-1), uN(jA)
    t = LD2(0,lr0-1,e+4); float uN3 = t.x;                 // uN(jB)
    t = LD2(1,lr0-1,e+2); float w0 = t.x, w1 = t.y;        // vN(jA-1), vN(jA)
    t = LD2(1,lr0-1,e+4); float w2 = t.x, w3 = t.y;        // vN(jB), vN(jB+1)
    t = LD2(2,lr0-1,e+2); float pN1 = t.y;                 // pN(jA)
    t = LD2(2,lr0-1,e+4); float pN2 = t.x;                 // pN(jB)
    t = LD2(3,lr0-1,e+2); float dN1 = t.y - pN1;
    t = LD2(3,lr0-1,e+4); float dN2 = t.x - pN2;
    // ---- row lr0-2: v only (for gn_prev of vn_prev) ----
    t = LD2(1,lr0-2,e+2); float vnnA = t.y;
    t = LD2(1,lr0-2,e+4); float vnnB = t.x;

    // ---- prologue fluxes (between rows ir0-1 and ir0) ----
    float prodNm = (0.5f*(w0+w1)) * (0.5f*(uN1+u1));
    float prodNA = (0.5f*(w1+w2)) * (0.5f*(uN2+u2));
    float prodNB = (0.5f*(w2+w3)) * (0.5f*(uN3+u3));
    float fnm = prodNm - (u1 - uN1);
    float fnA = prodNA - (u2 - uN2);
    float fnB = prodNB - (u3 - uN3);
    float gpa = 0.5f*(vnnA + w1); float gpA = gpa*gpa - (w1 - vnnA);
    float gpb = 0.5f*(vnnB + w2); float gpB = gpb*gpb - (w2 - vnnB);
    float geNm = prodNm - (w1 - w0);
    float geNA = prodNA - (w2 - w1);
    float geNB = prodNB - (w3 - w2);
    float ga2 = 0.5f*(w1 + v1); float gnA = ga2*ga2 - (v1 - w1);
    float gb2 = 0.5f*(w2 + v2); float gnB = gb2*gb2 - (v2 - w2);
    float dvNA = (-(geNA - geNm) - (gnA - gpA) - (p1 - pN1)) * 100.0f;
    float dvNB = (-(geNB - geNA) - (gnB - gpB) - (p2 - pN2)) * 100.0f;
    float vnA = w1 + dvNA * 0.001f;
    float vnB = w2 + dvNB * 0.001f;
    if (!INT) { if (ir0 - 1 < 1) { vnA = w1; vnB = w2; } }
    float vNA = w1, vNB = w2;          // v at previous row, cols jA, jB

    #pragma unroll
    for (int k = 0; k < 4; k++) {
        const int lr = lr0 + k;
        const int i  = ir0 + k;
        // ---- south-row loads: 9 LDS.64 cover everything ----
        t = LD2(0,lr+1,e);    float uS0 = t.y;
        t = LD2(0,lr+1,e+2);  float uS1 = t.x, uS2 = t.y;
        t = LD2(0,lr+1,e+4);  float uS3 = t.x, uS4 = t.y;
        t = LD2(1,lr+1,e+2);  float vS0 = t.x, vS1 = t.y;
        t = LD2(1,lr+1,e+4);  float vS2 = t.x, vS3 = t.y;
        t = LD2(2,lr+1,e+2);  float pS0 = t.x, pS1 = t.y;
        t = LD2(2,lr+1,e+4);  float pS2 = t.x, pS3 = t.y;
        t = LD2(3,lr+1,e+2);  float dS0 = t.x - pS0, dS1 = t.y - pS1;
        t = LD2(3,lr+1,e+4);  float dS2 = t.x - pS2, dS3 = t.y - pS3;

        // horizontal u fluxes: (jA-2,jA-1),(jA-1,jA),(jA,jB),(jB,jB+1)
        float ha = 0.5f*(u0+u1); float feA = ha*ha - (u1-u0);
        float hb = 0.5f*(u1+u2); float feB = hb*hb - (u2-u1);
        float hc = 0.5f*(u2+u3); float feC = hc*hc - (u3-u2);
        float hd = 0.5f*(u3+u4); float feD = hd*hd - (u4-u3);
        // shared cross products at cols jA-1, jA, jB
        float prodm = (0.5f*(v0+v1)) * (0.5f*(u1+uS1));
        float prodA = (0.5f*(v1+v2)) * (0.5f*(u2+uS2));
        float prodB = (0.5f*(v2+v3)) * (0.5f*(u3+uS3));
        float fn_m = prodm - (uS1-u1);
        float fn_A = prodA - (uS2-u2);
        float fn_B = prodB - (uS3-u3);
        float dum = (-(feB-feA) - (fn_m-fnm) - (p1-p0)) * 100.0f;
        float duA = (-(feC-feB) - (fn_A-fnA) - (p2-p1)) * 100.0f;
        float duB = (-(feD-feC) - (fn_B-fnB) - (p3-p2)) * 100.0f;
        float unm = u1 + dum * 0.001f;
        float unA = u2 + duA * 0.001f;
        float unB = u3 + duB * 0.001f;
        float gem = prodm - (v1-v0);
        float geA = prodA - (v2-v1);
        float geB = prodB - (v3-v2);
        float g2a = 0.5f*(v1+vS1); float gn_A = g2a*g2a - (vS1-v1);
        float g2b = 0.5f*(v2+vS2); float gn_B = g2b*g2b - (vS2-v2);
        float dvA = (-(geA-gem) - (gn_A-gnA) - (pS1-p1)) * 100.0f;
        float dvB = (-(geB-geA) - (gn_B-gnB) - (pS2-p2)) * 100.0f;
        float vn_A = v1 + dvA * 0.001f;
        float vn_B = v2 + dvB * 0.001f;
        if (!INT) {
            if (jA - 1 < 1 || i > 510) unm = u1;
            if (jA > 509    || i > 510) unA = u2;
            if (jB > 509    || i > 510) unB = u3;
            if (i > 509) { vn_A = v1; vn_B = v2; }
        }
        float contA = (u2-u1 + v1-vNA) * 100.0f;
        float contB = (u3-u2 + v2-vNB) * 100.0f;
        float bcvA = ((unA-unm) + (vn_A-vnA)) * 100000.0f;
        float bcvB = ((unB-unA) + (vn_B-vnB)) * 100000.0f;
        float lapA = 4.0f*d1 - d0 - d2 - dS1 - dN1;
        float lapB = 4.0f*d2 - d1 - d3 - dS2 - dN2;
        float poisA = fmaf(lapA, 10000.0f, bcvA);
        float poisB = fmaf(lapB, 10000.0f, bcvB);
        if (INT || (i <= 510 && jA <= 510)) { accC += fabsf(contA); accP += fabsf(poisA); }
        if (INT || (i <= 510 && jB <= 510)) { accC += fabsf(contB); accP += fabsf(poisB); }

        // ---- roll ----
        fnm = fn_m; fnA = fn_A; fnB = fn_B;
        gnA = gn_A; gnB = gn_B; vnA = vn_A; vnB = vn_B;
        vNA = v1; vNB = v2; dN1 = d1; dN2 = d2;
        u0=uS0; u1=uS1; u2=uS2; u3=uS3; u4=uS4;
        v0=vS0; v1=vS1; v2=vS2; v3=vS3;
        p0=pS0; p1=pS1; p2=pS2; p3=pS3;
        d0=dS0; d1=dS1; d2=dS2; d3=dS3;
    }
#undef LD2
}

__global__ __launch_bounds__(256, 4) void pil_kernel(const float* __restrict__ gen,
                                                     const float* __restrict__ pn,
                                                     float* __restrict__ out) {
    // planar halo tiles: sf[field][row][col], col window gx = bx*64-4 .. bx*64+67
    __shared__ __align__(16) float sf[4][TROWS][TCW];
    __shared__ float redC[8], redP[8];
    __shared__ double dred[8];
    __shared__ unsigned int s_ticket;

    const int bx = blockIdx.x, by = blockIdx.y, b = blockIdx.z;
    const int i0 = 1 + by * 32;
    const int j0 = 1 + bx * 64;
    const int tid = threadIdx.x;
    const int tx = tid & 31, ty = tid >> 5;   // ty = warp id, 0..7

    const float* u = gen + (size_t)b * 3 * S2;
    const float* v = u + S2;
    const float* p = v + S2;
    const float* q = pn + (size_t)b * S2;
    const int colbase = j0 - 5;               // = bx*64 - 4, 16B aligned

    // ---- per-lane 16B segment slots: 72 segs (4 fields x 18) over 32 lanes ----
    const int s1f = tx / 18,        s1c = tx - s1f * 18;
    const int s2  = tx + 32;
    const int s2f = s2 / 18,        s2c = s2 - s2f * 18;
    const int s3c = tx + 10;                         // field 3, lanes tx<8
    const float* fp1 = (s1f == 0) ? u : v;           // s1f in {0,1}
    const float* fp2 = (s2f == 1) ? v : (s2f == 2) ? p : q;
    float* dst1 = (float*)&sf[0][0][0] + s1f * (TROWS*TCW) + s1c * 4;
    float* dst2 = (float*)&sf[0][0][0] + s2f * (TROWS*TCW) + s2c * 4;
    float* dst3 = (float*)&sf[3][0][0] + s3c * 4;
    // edge-column segments that need clamping (bx 0: seg 0; bx 7: seg 17)
    const bool bad1 = (bx == 0 && s1c == 0) || (bx == 7 && s1c == 17);
    const bool bad2 = (bx == 0 && s2c == 0) || (bx == 7 && s2c == 17);
    const bool bad3 = (bx == 7 && s3c == 17);
    const int bcol = (bx == 0) ? 0 : (S - 1);

    // ---- load (dedup): warp ty fills rows ty*4..ty*4+3; warps 0-2 take rows 32-34 ----
    {
        const int o1 = colbase + s1c * 4;
        const int o2 = colbase + s2c * 4;
        const int o3 = colbase + s3c * 4;
        #pragma unroll
        for (int rl = 0; rl < 5; rl++) {
            int R = (rl < 4) ? (ty * 4 + rl) : (32 + ty);
            if (rl == 4 && ty >= 3) break;
            int gy = i0 - 2 + R; gy = max(0, min(S - 1, gy));
            const int ro = gy * S;
            if (!bad1) __pipeline_memcpy_async(dst1 + R * TCW, fp1 + ro + o1, 16);
            else { float vv = fp1[ro + bcol]; float* d = dst1 + R * TCW; d[0]=vv; d[1]=vv; d[2]=vv; d[3]=vv; }
            if (!bad2) __pipeline_memcpy_async(dst2 + R * TCW, fp2 + ro + o2, 16);
            else { float vv = fp2[ro + bcol]; float* d = dst2 + R * TCW; d[0]=vv; d[1]=vv; d[2]=vv; d[3]=vv; }
            if (tx < 8) {
                if (!bad3) __pipeline_memcpy_async(dst3 + R * TCW, q + ro + o3, 16);
                else { float vv = q[ro + bcol]; float* d = dst3 + R * TCW; d[0]=vv; d[1]=vv; d[2]=vv; d[3]=vv; }
            }
        }
    }
    __pipeline_commit();
    __pipeline_wait_prior(0);
    __syncthreads();

    float accC = 0.0f, accP = 0.0f;
    const bool interior = (bx >= 1) && (bx <= 6) && (by >= 1) && (by <= 14);
    if (interior) {
        tile_compute<true >(sf, tx, ty, i0, j0, accC, accP);
    } else {
        tile_compute<false>(sf, tx, ty, i0, j0, accC, accP);

        // ---- boundary-condition edge sums (edge blocks, from smem) ----
        float es = 0.0f; int eidx = -1;
        if (tid < 64) {                       // top/bottom: 64 cols (warps 0,1)
            int jj = j0 + tid, cc = tid + 5;
            if (by == 0) {                    // gy 0 -> R=1, gy 1 -> R=2
                eidx = 0;
                if (jj <= 509) es += sf[0][1][cc] + sf[0][2][cc];
                if (jj <= 510) es += sf[1][1][cc] + sf[2][1][cc];
            } else if (by == 15) {            // gy 510 -> R=31, gy 511 -> R=32
                eidx = 1;
                if (jj <= 509) es += 2.0f - (sf[0][31][cc] + sf[0][32][cc]);
                if (jj <= 510) es += sf[1][32][cc] + sf[2][32][cc];
            }
        } else if (tid < 96) {                // left/right: 32 rows (warp 2)
            int lane = tid - 64;              // 0..31
            int ii = i0 + lane, lrr = lane + 2;
            if (bx == 0) {                    // gx 0 -> c=4, gx 1 -> c=5
                eidx = 2;
                if (ii <= 509) es += sf[1][lrr][4] + sf[1][lrr][5];
                if (ii <= 510) es += sf[0][lrr][4] + sf[2][lrr][4];
            } else if (bx == 7) {             // gx 510 -> c=66, gx 511 -> c=67
                eidx = 3;
                if (ii <= 509) es += sf[1][lrr][67] + sf[1][lrr][66];
                if (ii <= 510) es += sf[0][lrr][67] + sf[2][lrr][67];
            }
        }
        if (eidx >= 0) {                      // warp-uniform per warp
            #pragma unroll
            for (int off = 16; off > 0; off >>= 1)
                es += __shfl_down_sync(0xFFFFFFFFu, es, off);
            if ((tid & 31) == 0)
                atomicAdd(&g_bc4[b * 4 + eidx], (double)es);
        }
    }

    // ---- block reduction of residual sums ----
    #pragma unroll
    for (int off = 16; off > 0; off >>= 1) {
        accC += __shfl_down_sync(0xFFFFFFFFu, accC, off);
        accP += __shfl_down_sync(0xFFFFFFFFu, accP, off);
    }
    if (tx == 0) { redC[ty] = accC; redP[ty] = accP; }
    __syncthreads();
    if (ty == 0) {
        float rc = (tx < 8) ? redC[tx] : 0.0f;
        float rp = (tx < 8) ? redP[tx] : 0.0f;
        #pragma unroll
        for (int off = 4; off > 0; off >>= 1) {
            rc += __shfl_down_sync(0xFFFFFFFFu, rc, off);
            rp += __shfl_down_sync(0xFFFFFFFFu, rp, off);
        }
        if (tx == 0) {
            atomicAdd(&g_acc[0], (double)rc);
            atomicAdd(&g_acc[1], (double)rp);
        }
    }

    // ---- last-block finalize ----
    __threadfence();
    if (tid == 0) s_ticket = atomicAdd(&g_count, 1u);
    __syncthreads();
    if (s_ticket == NBLK_TOTAL - 1u) {
        double mybc = 0.0;
        if (tid < NBATCH * 4)
            mybc = fabs(atomicAdd(&g_bc4[tid], 0.0));
        #pragma unroll
        for (int off = 16; off > 0; off >>= 1)
            mybc += __shfl_down_sync(0xFFFFFFFFu, mybc, off);
        if (tx == 0) dred[ty] = mybc;
        __syncthreads();
        if (tid == 0) {
            double bc = 0.0;
            #pragma unroll
            for (int kk = 0; kk < 8; kk++) bc += dred[kk];
            double C = atomicAdd(&g_acc[0], 0.0);
            double P = atomicAdd(&g_acc[1], 0.0);
            double denom = 32.0 * 510.0 * 510.0;
            out[0] = (float)(0.4 * (C / denom) + 0.2 * bc + (1.0 - 0.4 - 0.2) * (P / denom));
            g_acc[0] = 0.0; g_acc[1] = 0.0;
        }
        if (tid < NBATCH * 4) g_bc4[tid] = 0.0;
        __threadfence();
        __syncthreads();
        if (tid == 0) g_count = 0u;
    }
}

extern "C" void kernel_launch(void* const* d_in, const int* in_sizes, int n_in,
                              void* d_out, int out_size) {
    const float* gen = (const float*)d_in[0];
    const float* pn  = (const float*)d_in[1];
    float* out = (float*)d_out;
    dim3 grid(8, 16, NBATCH);   // 8 x 16 x 32 = 4096 blocks
    pil_kernel<<<grid, 256>>>(gen, pn, out);
}

// round 14
// speedup vs baseline: 1.2383x; 1.0833x over previous
#include <cuda_runtime.h>
#include <cuda_pipeline.h>

#define S  512
#define S2 (S*S)
#define NBATCH 32
#define NBLK_TOTAL 4096u
#define TROWS 35            // halo rows: 32 + 3
#define TCW   72            // smem row width (floats): 64 + halo, 16B-aligned

// Global accumulators (zero at load; finalize resets them each run)
__device__ double g_acc[2] = {0.0, 0.0};         // [0]=sum|cont|, [1]=sum|pois|
__device__ double g_bc4[NBATCH * 4] = {0.0};     // per-batch per-edge signed sums
__device__ unsigned int g_count = 0u;

// Per-thread strip: 2 columns (jA, jB) x 4 rows. Fields: 0=u,1=v,2=p,3=q.
// smem col c <-> gx = bx*64 - 4 + c ; col jA = j0+2*tx sits at c = 5+2*tx (odd),
// so all stencil windows tile into even-aligned float2 (LDS.64) pairs.
template<bool INT>
__device__ __forceinline__ void tile_compute(
    const float (*__restrict__ sf)[TROWS][TCW],
    int tx, int ty, int i0, int j0, float& accC, float& accP)
{
    const int e   = 2 + 2 * tx;      // even base col: pairs at e, e+2, e+4
    const int lr0 = ty * 4 + 2;
    const int ir0 = i0 + ty * 4;
    const int jA  = j0 + 2 * tx;
    const int jB  = jA + 1;

#define LD2(F,R,C) (*(const float2*)(&sf[F][R][C]))

    float2 t;
    // ---- current row lr0: u(jA-2..jA+2), v/p/d(jA-1..jB+1) ----
    t = LD2(0,lr0,e);    float u0 = t.y;
    t = LD2(0,lr0,e+2);  float u1 = t.x, u2 = t.y;
    t = LD2(0,lr0,e+4);  float u3 = t.x, u4 = t.y;
    t = LD2(1,lr0,e+2);  float v0 = t.x, v1 = t.y;
    t = LD2(1,lr0,e+4);  float v2 = t.x, v3 = t.y;
    t = LD2(2,lr0,e+2);  float p0 = t.x, p1 = t.y;
    t = LD2(2,lr0,e+4);  float p2 = t.x, p3 = t.y;
    t = LD2(3,lr0,e+2);  float d0 = t.x - p0, d1 = t.y - p1;
    t = LD2(3,lr0,e+4);  float d2 = t.x - p2, d3 = t.y - p3;
    // ---- row lr0-1 (north) ----
    t = LD2(0,lr0-1,e+2); float uN1 = t.x, uN2 = t.y;      // uN(jA-1), uN(jA)
    t = LD2(0,lr0-1,e+4); float uN3 = t.x;                 // uN(jB)
    t = LD2(1,lr0-1,e+2); float w0 = t.x, w1 = t.y;        // vN(jA-1), vN(jA)
    t = LD2(1,lr0-1,e+4); float w2 = t.x, w3 = t.y;        // vN(jB), vN(jB+1)
    t = LD2(2,lr0-1,e+2); float pN1 = t.y;                 // pN(jA)
    t = LD2(2,lr0-1,e+4); float pN2 = t.x;                 // pN(jB)
    t = LD2(3,lr0-1,e+2); float dN1 = t.y - pN1;
    t = LD2(3,lr0-1,e+4); float dN2 = t.x - pN2;
    // ---- row lr0-2: v only (for gn_prev of vn_prev) ----
    t = LD2(1,lr0-2,e+2); float vnnA = t.y;
    t = LD2(1,lr0-2,e+4); float vnnB = t.x;

    // ---- prologue fluxes (between rows ir0-1 and ir0) ----
    float prodNm = (0.5f*(w0+w1)) * (0.5f*(uN1+u1));
    float prodNA = (0.5f*(w1+w2)) * (0.5f*(uN2+u2));
    float prodNB = (0.5f*(w2+w3)) * (0.5f*(uN3+u3));
    float fnm = prodNm - (u1 - uN1);
    float fnA = prodNA - (u2 - uN2);
    float fnB = prodNB - (u3 - uN3);
    float gpa = 0.5f*(vnnA + w1); float gpA = gpa*gpa - (w1 - vnnA);
    float gpb = 0.5f*(vnnB + w2); float gpB = gpb*gpb - (w2 - vnnB);
    float geNm = prodNm - (w1 - w0);
    float geNA = prodNA - (w2 - w1);
    float geNB = prodNB - (w3 - w2);
    float ga2 = 0.5f*(w1 + v1); float gnA = ga2*ga2 - (v1 - w1);
    float gb2 = 0.5f*(w2 + v2); float gnB = gb2*gb2 - (v2 - w2);
    float dvNA = (-(geNA - geNm) - (gnA - gpA) - (p1 - pN1)) * 100.0f;
    float dvNB = (-(geNB - geNA) - (gnB - gpB) - (p2 - pN2)) * 100.0f;
    float vnA = w1 + dvNA * 0.001f;
    float vnB = w2 + dvNB * 0.001f;
    if (!INT) { if (ir0 - 1 < 1) { vnA = w1; vnB = w2; } }
    float vNA = w1, vNB = w2;          // v at previous row, cols jA, jB

    #pragma unroll
    for (int k = 0; k < 4; k++) {
        const int lr = lr0 + k;
        const int i  = ir0 + k;
        // ---- south-row loads: 9 LDS.64 cover everything ----
        t = LD2(0,lr+1,e);    float uS0 = t.y;
        t = LD2(0,lr+1,e+2);  float uS1 = t.x, uS2 = t.y;
        t = LD2(0,lr+1,e+4);  float uS3 = t.x, uS4 = t.y;
        t = LD2(1,lr+1,e+2);  float vS0 = t.x, vS1 = t.y;
        t = LD2(1,lr+1,e+4);  float vS2 = t.x, vS3 = t.y;
        t = LD2(2,lr+1,e+2);  float pS0 = t.x, pS1 = t.y;
        t = LD2(2,lr+1,e+4);  float pS2 = t.x, pS3 = t.y;
        t = LD2(3,lr+1,e+2);  float dS0 = t.x - pS0, dS1 = t.y - pS1;
        t = LD2(3,lr+1,e+4);  float dS2 = t.x - pS2, dS3 = t.y - pS3;

        // horizontal u fluxes: (jA-2,jA-1),(jA-1,jA),(jA,jB),(jB,jB+1)
        float ha = 0.5f*(u0+u1); float feA = ha*ha - (u1-u0);
        float hb = 0.5f*(u1+u2); float feB = hb*hb - (u2-u1);
        float hc = 0.5f*(u2+u3); float feC = hc*hc - (u3-u2);
        float hd = 0.5f*(u3+u4); float feD = hd*hd - (u4-u3);
        // shared cross products at cols jA-1, jA, jB
        float prodm = (0.5f*(v0+v1)) * (0.5f*(u1+uS1));
        float prodA = (0.5f*(v1+v2)) * (0.5f*(u2+uS2));
        float prodB = (0.5f*(v2+v3)) * (0.5f*(u3+uS3));
        float fn_m = prodm - (uS1-u1);
        float fn_A = prodA - (uS2-u2);
        float fn_B = prodB - (uS3-u3);
        float dum = (-(feB-feA) - (fn_m-fnm) - (p1-p0)) * 100.0f;
        float duA = (-(feC-feB) - (fn_A-fnA) - (p2-p1)) * 100.0f;
        float duB = (-(feD-feC) - (fn_B-fnB) - (p3-p2)) * 100.0f;
        float unm = u1 + dum * 0.001f;
        float unA = u2 + duA * 0.001f;
        float unB = u3 + duB * 0.001f;
        float gem = prodm - (v1-v0);
        float geA = prodA - (v2-v1);
        float geB = prodB - (v3-v2);
        float g2a = 0.5f*(v1+vS1); float gn_A = g2a*g2a - (vS1-v1);
        float g2b = 0.5f*(v2+vS2); float gn_B = g2b*g2b - (vS2-v2);
        float dvA = (-(geA-gem) - (gn_A-gnA) - (pS1-p1)) * 100.0f;
        float dvB = (-(geB-geA) - (gn_B-gnB) - (pS2-p2)) * 100.0f;
        float vn_A = v1 + dvA * 0.001f;
        float vn_B = v2 + dvB * 0.001f;
        if (!INT) {
            const bool rowbad = (i > 510);
            if (jA - 1 < 1 || rowbad) unm = u1;
            if (jA > 509    || rowbad) unA = u2;
            if (jB > 509    || rowbad) unB = u3;
            if (i > 509) { vn_A = v1; vn_B = v2; }
        }
        float contA = (u2-u1 + v1-vNA) * 100.0f;
        float contB = (u3-u2 + v2-vNB) * 100.0f;
        float bcvA = ((unA-unm) + (vn_A-vnA)) * 100000.0f;
        float bcvB = ((unB-unA) + (vn_B-vnB)) * 100000.0f;
        float lapA = 4.0f*d1 - d0 - d2 - dS1 - dN1;
        float lapB = 4.0f*d2 - d1 - d3 - dS2 - dN2;
        float poisA = fmaf(lapA, 10000.0f, bcvA);
        float poisB = fmaf(lapB, 10000.0f, bcvB);
        if (INT || (i <= 510 && jA <= 510)) { accC += fabsf(contA); accP += fabsf(poisA); }
        if (INT || (i <= 510 && jB <= 510)) { accC += fabsf(contB); accP += fabsf(poisB); }

        // ---- roll ----
        fnm = fn_m; fnA = fn_A; fnB = fn_B;
        gnA = gn_A; gnB = gn_B; vnA = vn_A; vnB = vn_B;
        vNA = v1; vNB = v2; dN1 = d1; dN2 = d2;
        u0=uS0; u1=uS1; u2=uS2; u3=uS3; u4=uS4;
        v0=vS0; v1=vS1; v2=vS2; v3=vS3;
        p0=pS0; p1=pS1; p2=pS2; p3=pS3;
        d0=dS0; d1=dS1; d2=dS2; d3=dS3;
    }
#undef LD2
}

__global__ __launch_bounds__(256, 5) void pil_kernel(const float* __restrict__ gen,
                                                     const float* __restrict__ pn,
                                                     float* __restrict__ out) {
    // planar halo tiles: sf[field][row][col], col window gx = bx*64-4 .. bx*64+67
    __shared__ __align__(16) float sf[4][TROWS][TCW];
    __shared__ float redC[8], redP[8];
    __shared__ double dred[8];
    __shared__ unsigned int s_ticket;

    const int bx = blockIdx.x, by = blockIdx.y, b = blockIdx.z;
    const int i0 = 1 + by * 32;
    const int j0 = 1 + bx * 64;
    const int tid = threadIdx.x;
    const int tx = tid & 31, ty = tid >> 5;   // ty = warp id, 0..7

    const float* u = gen + (size_t)b * 3 * S2;
    const float* v = u + S2;
    const float* p = v + S2;
    const float* q = pn + (size_t)b * S2;
    const int colbase = j0 - 5;               // = bx*64 - 4, 16B aligned

    // ---- per-lane 16B segment slots: 72 segs (4 fields x 18) over 32 lanes ----
    const int s1f = tx / 18,        s1c = tx - s1f * 18;
    const int s2  = tx + 32;
    const int s2f = s2 / 18,        s2c = s2 - s2f * 18;
    const int s3c = tx + 10;                         // field 3, lanes tx<8
    const float* fp1 = (s1f == 0) ? u : v;           // s1f in {0,1}
    const float* fp2 = (s2f == 1) ? v : (s2f == 2) ? p : q;
    float* dst1 = (float*)&sf[0][0][0] + s1f * (TROWS*TCW) + s1c * 4;
    float* dst2 = (float*)&sf[0][0][0] + s2f * (TROWS*TCW) + s2c * 4;
    float* dst3 = (float*)&sf[3][0][0] + s3c * 4;
    // edge-column segments that need clamping (bx 0: seg 0; bx 7: seg 17)
    const bool bad1 = (bx == 0 && s1c == 0) || (bx == 7 && s1c == 17);
    const bool bad2 = (bx == 0 && s2c == 0) || (bx == 7 && s2c == 17);
    const bool bad3 = (bx == 7 && s3c == 17);
    const int bcol = (bx == 0) ? 0 : (S - 1);

    // ---- load (dedup): warp ty fills rows ty*4..ty*4+3; warps 0-2 take rows 32-34 ----
    {
        const int o1 = colbase + s1c * 4;
        const int o2 = colbase + s2c * 4;
        const int o3 = colbase + s3c * 4;
        #pragma unroll
        for (int rl = 0; rl < 5; rl++) {
            int R = (rl < 4) ? (ty * 4 + rl) : (32 + ty);
            if (rl == 4 && ty >= 3) break;
            int gy = i0 - 2 + R; gy = max(0, min(S - 1, gy));
            const int ro = gy * S;
            if (!bad1) __pipeline_memcpy_async(dst1 + R * TCW, fp1 + ro + o1, 16);
            else { float vv = fp1[ro + bcol]; float* d = dst1 + R * TCW; d[0]=vv; d[1]=vv; d[2]=vv; d[3]=vv; }
            if (!bad2) __pipeline_memcpy_async(dst2 + R * TCW, fp2 + ro + o2, 16);
            else { float vv = fp2[ro + bcol]; float* d = dst2 + R * TCW; d[0]=vv; d[1]=vv; d[2]=vv; d[3]=vv; }
            if (tx < 8) {
                if (!bad3) __pipeline_memcpy_async(dst3 + R * TCW, q + ro + o3, 16);
                else { float vv = q[ro + bcol]; float* d = dst3 + R * TCW; d[0]=vv; d[1]=vv; d[2]=vv; d[3]=vv; }
            }
        }
    }
    __pipeline_commit();
    __pipeline_wait_prior(0);
    __syncthreads();

    float accC = 0.0f, accP = 0.0f;
    const bool interior = (bx >= 1) && (bx <= 6) && (by >= 1) && (by <= 14);
    if (interior) {
        tile_compute<true >(sf, tx, ty, i0, j0, accC, accP);
    } else {
        tile_compute<false>(sf, tx, ty, i0, j0, accC, accP);

        // ---- boundary-condition edge sums (edge blocks, from smem) ----
        float es = 0.0f; int eidx = -1;
        if (tid < 64) {                       // top/bottom: 64 cols (warps 0,1)
            int jj = j0 + tid, cc = tid + 5;
            if (by == 0) {                    // gy 0 -> R=1, gy 1 -> R=2
                eidx = 0;
                if (jj <= 509) es += sf[0][1][cc] + sf[0][2][cc];
                if (jj <= 510) es += sf[1][1][cc] + sf[2][1][cc];
            } else if (by == 15) {            // gy 510 -> R=31, gy 511 -> R=32
                eidx = 1;
                if (jj <= 509) es += 2.0f - (sf[0][31][cc] + sf[0][32][cc]);
                if (jj <= 510) es += sf[1][32][cc] + sf[2][32][cc];
            }
        } else if (tid < 96) {                // left/right: 32 rows (warp 2)
            int lane = tid - 64;              // 0..31
            int ii = i0 + lane, lrr = lane + 2;
            if (bx == 0) {                    // gx 0 -> c=4, gx 1 -> c=5
                eidx = 2;
                if (ii <= 509) es += sf[1][lrr][4] + sf[1][lrr][5];
                if (ii <= 510) es += sf[0][lrr][4] + sf[2][lrr][4];
            } else if (bx == 7) {             // gx 510 -> c=66, gx 511 -> c=67
                eidx = 3;
                if (ii <= 509) es += sf[1][lrr][67] + sf[1][lrr][66];
                if (ii <= 510) es += sf[0][lrr][67] + sf[2][lrr][67];
            }
        }
        if (eidx >= 0) {                      // warp-uniform per warp
            #pragma unroll
            for (int off = 16; off > 0; off >>= 1)
                es += __shfl_down_sync(0xFFFFFFFFu, es, off);
            if ((tid & 31) == 0)
                atomicAdd(&g_bc4[b * 4 + eidx], (double)es);
        }
    }

    // ---- block reduction of residual sums ----
    #pragma unroll
    for (int off = 16; off > 0; off >>= 1) {
        accC += __shfl_down_sync(0xFFFFFFFFu, accC, off);
        accP += __shfl_down_sync(0xFFFFFFFFu, accP, off);
    }
    if (tx == 0) { redC[ty] = accC; redP[ty] = accP; }
    __syncthreads();
    if (ty == 0) {
        float rc = (tx < 8) ? redC[tx] : 0.0f;
        float rp = (tx < 8) ? redP[tx] : 0.0f;
        #pragma unroll
        for (int off = 4; off > 0; off >>= 1) {
            rc += __shfl_down_sync(0xFFFFFFFFu, rc, off);
            rp += __shfl_down_sync(0xFFFFFFFFu, rp, off);
        }
        if (tx == 0) {
            atomicAdd(&g_acc[0], (double)rc);
            atomicAdd(&g_acc[1], (double)rp);
        }
    }

    // ---- last-block finalize ----
    __threadfence();
    if (tid == 0) s_ticket = atomicAdd(&g_count, 1u);
    __syncthreads();
    if (s_ticket == NBLK_TOTAL - 1u) {
        double mybc = 0.0;
        if (tid < NBATCH * 4)
            mybc = fabs(atomicAdd(&g_bc4[tid], 0.0));
        #pragma unroll
        for (int off = 16; off > 0; off >>= 1)
            mybc += __shfl_down_sync(0xFFFFFFFFu, mybc, off);
        if (tx == 0) dred[ty] = mybc;
        __syncthreads();
        if (tid == 0) {
            double bc = 0.0;
            #pragma unroll
            for (int kk = 0; kk < 8; kk++) bc += dred[kk];
            double C = atomicAdd(&g_acc[0], 0.0);
            double P = atomicAdd(&g_acc[1], 0.0);
            double denom = 32.0 * 510.0 * 510.0;
            out[0] = (float)(0.4 * (C / denom) + 0.2 * bc + (1.0 - 0.4 - 0.2) * (P / denom));
            g_acc[0] = 0.0; g_acc[1] = 0.0;
        }
        if (tid < NBATCH * 4) g_bc4[tid] = 0.0;
        __threadfence();
        __syncthreads();
        if (tid == 0) g_count = 0u;
    }
}

extern "C" void kernel_launch(void* const* d_in, const int* in_sizes, int n_in,
                              void* d_out, int out_size) {
    const float* gen = (const float*)d_in[0];
    const float* pn  = (const float*)d_in[1];
    float* out = (float*)d_out;
    dim3 grid(8, 16, NBATCH);   // 8 x 16 x 32 = 4096 blocks
    pil_kernel<<<grid, 256>>>(gen, pn, out);
}